// round 3
// baseline (speedup 1.0000x reference)
#include <cuda_runtime.h>
#include <cuda_bf16.h>
#include <cstdint>

// Inputs (metadata order):
// 0: stimulus_set int32 [B,5]
// 1: table        f32   [21,3]
// 2: w            f32   [3]
// 3: rho 4: beta 5: tau 6: gamma 7: upper 8: midpoint 9: rate  (all f32[1])
// Output: concat(output_rank [B,4], output_rt [B,1]) f32

#define ROWS_PER_GROUP 4
#define N_TAB 21
#define N_PAIRS (N_TAB * N_TAB)   // 441
#define N_REP 16                  // bank replication: lane reads column (lane & 15)
#define TAB_ELEMS (N_PAIRS * N_REP)
#define SMEM_BYTES (TAB_ELEMS * 8)
#define BLOCK 512
#define GRID  444                 // 3 blocks/SM * 148 SMs (persistent-ish)

__global__ __launch_bounds__(BLOCK) void rankrt_kernel(
    const int4* __restrict__ stim4,      // [B*5/4] int4 view
    const float* __restrict__ table,     // [21*3]
    const float* __restrict__ w,
    const float* __restrict__ rho_p, const float* __restrict__ beta_p,
    const float* __restrict__ tau_p, const float* __restrict__ gamma_p,
    const float* __restrict__ upper_p, const float* __restrict__ midpoint_p,
    const float* __restrict__ rate_p,
    float* __restrict__ rank_out,        // [B*4]
    float* __restrict__ rt_out,          // [B]
    int n_groups)                        // B / ROWS_PER_GROUP
{
    // ptab[(q*21+r)*16 + c] = { s(q,r), s*log(s) }, replicated over c=0..15 so
    // lane l (using c = l&15) always hits bank-pair (2c,2c+1): conflict-free.
    extern __shared__ float2 ptab[];

    const float w0 = __ldg(w), w1 = __ldg(w + 1), w2 = __ldg(w + 2);
    const float rho = __ldg(rho_p), beta = __ldg(beta_p), tau = __ldg(tau_p);
    const float gamma = __ldg(gamma_p), upper = __ldg(upper_p);
    const float midpoint = __ldg(midpoint_p), rate = __ldg(rate_p);
    const bool rho2 = (rho == 2.0f);
    const bool tau1 = (tau == 1.0f);
    const float inv_rho = 1.0f / rho;

    // Build replicated pair table. Linear writes -> conflict-free STS.
    for (int idx = threadIdx.x; idx < TAB_ELEMS; idx += BLOCK) {
        int e = idx >> 4;           // pair index
        int q = e / N_TAB;
        int r = e - q * N_TAB;
        float dx = fabsf(__ldg(table + q * 3 + 0) - __ldg(table + r * 3 + 0));
        float dy = fabsf(__ldg(table + q * 3 + 1) - __ldg(table + r * 3 + 1));
        float dz = fabsf(__ldg(table + q * 3 + 2) - __ldg(table + r * 3 + 2));
        float d;
        if (rho2) {
            float dsq = fmaf(w0, dx * dx, fmaf(w1, dy * dy, w2 * dz * dz));
            d = sqrtf(dsq);
        } else {
            float acc = w0 * __powf(dx, rho) + w1 * __powf(dy, rho) + w2 * __powf(dz, rho);
            d = __powf(acc, inv_rho);
        }
        float dt = tau1 ? d : __powf(d, tau);
        float s = __expf(-beta * dt) + gamma;
        ptab[idx] = make_float2(s, s * __logf(s));
    }
    __syncthreads();

    const int lane_c = threadIdx.x & (N_REP - 1);
    const int stride = GRID * BLOCK;

    for (int g = blockIdx.x * BLOCK + threadIdx.x; g < n_groups; g += stride) {
        // 4 rows * 5 ints = 20 ints = 5 int4 loads (16B-aligned at g*80 bytes)
        int idx[20];
        #pragma unroll
        for (int v = 0; v < 5; v++) {
            int4 p = stim4[g * 5 + v];
            idx[v * 4 + 0] = p.x; idx[v * 4 + 1] = p.y;
            idx[v * 4 + 2] = p.z; idx[v * 4 + 3] = p.w;
        }

        float rt4[ROWS_PER_GROUP];

        #pragma unroll
        for (int r = 0; r < ROWS_PER_GROUP; r++) {
            const int* row = idx + r * 5;
            int qbase = row[0] * N_TAB;

            float2 p0 = ptab[((qbase + row[1]) << 4) | lane_c];
            float2 p1 = ptab[((qbase + row[2]) << 4) | lane_c];
            float2 p2 = ptab[((qbase + row[3]) << 4) | lane_c];
            float2 p3 = ptab[((qbase + row[4]) << 4) | lane_c];

            float ssum  = (p0.x + p1.x) + (p2.x + p3.x);
            float slsum = (p0.y + p1.y) + (p2.y + p3.y);

            float inv = __frcp_rn(ssum);
            // H = log(S) - (sum s*log s)/S
            float ent = __logf(ssum) - slsum * inv;

            float4 rv = make_float4(p0.x * inv, p1.x * inv, p2.x * inv, p3.x * inv);
            reinterpret_cast<float4*>(rank_out)[g * ROWS_PER_GROUP + r] = rv;

            rt4[r] = upper * __frcp_rn(1.0f + __expf(-rate * (ent - midpoint)));
        }

        reinterpret_cast<float4*>(rt_out)[g] =
            make_float4(rt4[0], rt4[1], rt4[2], rt4[3]);
    }
}

extern "C" void kernel_launch(void* const* d_in, const int* in_sizes, int n_in,
                              void* d_out, int out_size) {
    const int* stim = (const int*)d_in[0];
    const float* table = (const float*)d_in[1];
    const float* w = (const float*)d_in[2];
    const float* rho_p = (const float*)d_in[3];
    const float* beta_p = (const float*)d_in[4];
    const float* tau_p = (const float*)d_in[5];
    const float* gamma_p = (const float*)d_in[6];
    const float* upper_p = (const float*)d_in[7];
    const float* midpoint_p = (const float*)d_in[8];
    const float* rate_p = (const float*)d_in[9];

    int B = in_sizes[0] / 5;
    float* rank_out = (float*)d_out;                 // B*4
    float* rt_out = (float*)d_out + (size_t)B * 4;   // B

    int n_groups = B / ROWS_PER_GROUP;               // B divisible by 4

    cudaFuncSetAttribute(rankrt_kernel,
                         cudaFuncAttributeMaxDynamicSharedMemorySize, SMEM_BYTES);

    rankrt_kernel<<<GRID, BLOCK, SMEM_BYTES>>>(
        (const int4*)stim, table, w, rho_p, beta_p, tau_p, gamma_p,
        upper_p, midpoint_p, rate_p, rank_out, rt_out, n_groups);
}

// round 4
// speedup vs baseline: 1.2723x; 1.2723x over previous
#include <cuda_runtime.h>
#include <cuda_bf16.h>
#include <cstdint>

// Inputs (metadata order):
// 0: stimulus_set int32 [B,5]
// 1: table        f32   [21,3]
// 2: w            f32   [3]
// 3: rho 4: beta 5: tau 6: gamma 7: upper 8: midpoint 9: rate  (all f32[1])
// Output: concat(output_rank [B,4], output_rt [B,1]) f32

#define ROWS_PER_THREAD 4
#define N_TAB 21
#define N_PAIRS (N_TAB * N_TAB)   // 441
#define BLOCK 256

__global__ __launch_bounds__(BLOCK) void rankrt_kernel(
    const int4* __restrict__ stim4,      // [B*5/4] int4 view
    const float* __restrict__ table,     // [21*3]
    const float* __restrict__ w,
    const float* __restrict__ rho_p, const float* __restrict__ beta_p,
    const float* __restrict__ tau_p, const float* __restrict__ gamma_p,
    const float* __restrict__ upper_p, const float* __restrict__ midpoint_p,
    const float* __restrict__ rate_p,
    float* __restrict__ rank_out,        // [B*4]
    float* __restrict__ rt_out,          // [B]
    int n_threads)                       // B / ROWS_PER_THREAD
{
    // pair_tab[q*21+r] = { s(q,r), s*log(s) }
    __shared__ float2 pair_tab[N_PAIRS];

    const int t = blockIdx.x * blockDim.x + threadIdx.x;
    const bool active = (t < n_threads);

    // ---- Prefetch index loads FIRST (streaming: no reuse inside launch) ----
    int4 pv[5];
    if (active) {
        #pragma unroll
        for (int v = 0; v < 5; v++)
            pv[v] = __ldcs(stim4 + (size_t)t * 5 + v);
    }

    // ---- Build 441-entry pair table (overlaps with the loads above) ----
    const float w0 = __ldg(w), w1 = __ldg(w + 1), w2 = __ldg(w + 2);
    const float rho = __ldg(rho_p), beta = __ldg(beta_p), tau = __ldg(tau_p);
    const float gamma = __ldg(gamma_p), upper = __ldg(upper_p);
    const float midpoint = __ldg(midpoint_p), rate = __ldg(rate_p);
    const bool rho2 = (rho == 2.0f);
    const bool tau1 = (tau == 1.0f);
    const float inv_rho = 1.0f / rho;

    for (int e = threadIdx.x; e < N_PAIRS; e += BLOCK) {
        int q = e / N_TAB;
        int r = e - q * N_TAB;
        float dx = fabsf(__ldg(table + q * 3 + 0) - __ldg(table + r * 3 + 0));
        float dy = fabsf(__ldg(table + q * 3 + 1) - __ldg(table + r * 3 + 1));
        float dz = fabsf(__ldg(table + q * 3 + 2) - __ldg(table + r * 3 + 2));
        float d;
        if (rho2) {
            float dsq = fmaf(w0, dx * dx, fmaf(w1, dy * dy, w2 * dz * dz));
            d = sqrtf(dsq);
        } else {
            float acc = w0 * __powf(dx, rho) + w1 * __powf(dy, rho) + w2 * __powf(dz, rho);
            d = __powf(acc, inv_rho);
        }
        float dt = tau1 ? d : __powf(d, tau);
        float s = __expf(-beta * dt) + gamma;
        pair_tab[e] = make_float2(s, s * __logf(s));
    }
    __syncthreads();

    if (!active) return;

    int idx[20];
    #pragma unroll
    for (int v = 0; v < 5; v++) {
        idx[v * 4 + 0] = pv[v].x; idx[v * 4 + 1] = pv[v].y;
        idx[v * 4 + 2] = pv[v].z; idx[v * 4 + 3] = pv[v].w;
    }

    float rt4[ROWS_PER_THREAD];

    #pragma unroll
    for (int r = 0; r < ROWS_PER_THREAD; r++) {
        const int* row = idx + r * 5;
        const float2* qrow = pair_tab + row[0] * N_TAB;

        float2 p0 = qrow[row[1]];
        float2 p1 = qrow[row[2]];
        float2 p2 = qrow[row[3]];
        float2 p3 = qrow[row[4]];

        float ssum  = (p0.x + p1.x) + (p2.x + p3.x);
        float slsum = (p0.y + p1.y) + (p2.y + p3.y);

        float inv = __frcp_rn(ssum);
        // H = log(S) - (sum s*log s)/S
        float ent = __logf(ssum) - slsum * inv;

        float4 rv = make_float4(p0.x * inv, p1.x * inv, p2.x * inv, p3.x * inv);
        __stcs(reinterpret_cast<float4*>(rank_out) + (size_t)t * ROWS_PER_THREAD + r, rv);

        rt4[r] = upper * __frcp_rn(1.0f + __expf(-rate * (ent - midpoint)));
    }

    __stcs(reinterpret_cast<float4*>(rt_out) + t,
           make_float4(rt4[0], rt4[1], rt4[2], rt4[3]));
}

extern "C" void kernel_launch(void* const* d_in, const int* in_sizes, int n_in,
                              void* d_out, int out_size) {
    const int* stim = (const int*)d_in[0];
    const float* table = (const float*)d_in[1];
    const float* w = (const float*)d_in[2];
    const float* rho_p = (const float*)d_in[3];
    const float* beta_p = (const float*)d_in[4];
    const float* tau_p = (const float*)d_in[5];
    const float* gamma_p = (const float*)d_in[6];
    const float* upper_p = (const float*)d_in[7];
    const float* midpoint_p = (const float*)d_in[8];
    const float* rate_p = (const float*)d_in[9];

    int B = in_sizes[0] / 5;
    float* rank_out = (float*)d_out;                 // B*4
    float* rt_out = (float*)d_out + (size_t)B * 4;   // B

    int n_threads = B / ROWS_PER_THREAD;             // B divisible by 4
    int grid = (n_threads + BLOCK - 1) / BLOCK;
    rankrt_kernel<<<grid, BLOCK>>>(
        (const int4*)stim, table, w, rho_p, beta_p, tau_p, gamma_p,
        upper_p, midpoint_p, rate_p, rank_out, rt_out, n_threads);
}